// round 15
// baseline (speedup 1.0000x reference)
#include <cuda_runtime.h>
#include <cstdint>

// SlidingKVQCache on GB300 — FINAL roofline kernel (locked, session best).
//
// out = concat over {k,v,q} of (cache shifted left 1 token, token appended).
// Caches [4,32,2048,128] fp32, tokens [4,32,1,128]. 768 MiB mandatory traffic.
// Measured 6.71 TB/s = 84.6% of 8 TB/s spec — the empirical HBM3e ceiling for
// a 1:1 read:write stream. Ten structural variants converged at this band;
// SM-side pipes are all <10% busy. This is the roofline solution.
//
// Flat per-cache view (float4 units): slab = 2048*32 = 65536 = 2^16 per (b,h).
//   out[i] = cache[i + 32]                         if (i & 65535) < 65504
//   out[i] = tok[(i>>16)*32 + ((i&65535)-65504)]   otherwise (last token row)
//
// Body: U=4 front-batched plain LDG.128 (MLP=4/thread), plain STG.128,
// 256-thread CTAs, grid (8192, 3).

static constexpr unsigned SLABMASK = 65535u;
static constexpr unsigned TAIL4    = 65504u;
static constexpr unsigned CACHE4   = 1u << 23;          // 8388608 float4 per cache

static constexpr int THREADS = 256;
static constexpr int U = 4;                             // float4 per thread
static constexpr unsigned PER_BLOCK = THREADS * U;      // 1024

__global__ __launch_bounds__(THREADS, 8)
void sliding_cache_flat_kernel(
    const float4* __restrict__ kc,
    const float4* __restrict__ vc,
    const float4* __restrict__ qc,
    const float4* __restrict__ kt,
    const float4* __restrict__ vt,
    const float4* __restrict__ qt,
    float4* __restrict__ out)
{
    const int c = blockIdx.y;
    const float4* __restrict__ cache = (c == 0) ? kc : (c == 1) ? vc : qc;
    const float4* __restrict__ tok   = (c == 0) ? kt : (c == 1) ? vt : qt;
    float4* __restrict__ ob = out + (size_t)c * CACHE4;

    const unsigned base = blockIdx.x * PER_BLOCK + threadIdx.x;

    unsigned idx[U];
    const float4* __restrict__ src[U];

    #pragma unroll
    for (int k = 0; k < U; k++) {
        idx[k] = base + (unsigned)k * THREADS;
        unsigned pos = idx[k] & SLABMASK;
        src[k] = (pos < TAIL4)
               ? cache + idx[k] + 32
               : tok + ((idx[k] >> 16) << 5) + (pos - TAIL4);
    }

    float4 v[U];
    #pragma unroll
    for (int k = 0; k < U; k++) v[k] = *src[k];      // front-batched LDG.128 x4

    #pragma unroll
    for (int k = 0; k < U; k++) ob[idx[k]] = v[k];   // plain STG.128
}

extern "C" void kernel_launch(void* const* d_in, const int* in_sizes, int n_in,
                              void* d_out, int out_size)
{
    const float4* kc = (const float4*)d_in[0];
    const float4* vc = (const float4*)d_in[1];
    const float4* qc = (const float4*)d_in[2];
    const float4* kt = (const float4*)d_in[3];
    const float4* vt = (const float4*)d_in[4];
    const float4* qt = (const float4*)d_in[5];
    float4* out = (float4*)d_out;

    dim3 grid(CACHE4 / PER_BLOCK, 3, 1);   // 8192 x 3 = 24576 blocks
    sliding_cache_flat_kernel<<<grid, THREADS>>>(kc, vc, qc, kt, vt, qt, out);
}

// round 16
// speedup vs baseline: 1.0057x; 1.0057x over previous
#include <cuda_runtime.h>
#include <cstdint>

// SlidingKVQCache on GB300 — FINAL roofline kernel (locked, session best).
//
// out = concat over {k,v,q} of (cache shifted left 1 token, token appended).
// Caches [4,32,2048,128] fp32, tokens [4,32,1,128]. 768 MiB mandatory traffic.
// Measured 6.71 TB/s = 84.6% of 8 TB/s spec — the empirical HBM3e ceiling for
// a 1:1 read:write stream (10+ structural variants converged here; SM-side
// pipes <10% busy; CE path, persistence, hints, vector width all eliminated).
//
// Flat per-cache view (float4 units): slab = 2048*32 = 65536 = 2^16 per (b,h).
//   out[i] = cache[i + 32]                         if (i & 65535) < 65504
//   out[i] = tok[(i>>16)*32 + ((i&65535)-65504)]   otherwise (last token row)
//
// Body: U=4 front-batched plain LDG.128 (MLP=4/thread), plain STG.128,
// 256-thread CTAs, grid (8192, 3).

static constexpr unsigned SLABMASK = 65535u;
static constexpr unsigned TAIL4    = 65504u;
static constexpr unsigned CACHE4   = 1u << 23;          // 8388608 float4 per cache

static constexpr int THREADS = 256;
static constexpr int U = 4;                             // float4 per thread
static constexpr unsigned PER_BLOCK = THREADS * U;      // 1024

__global__ __launch_bounds__(THREADS, 8)
void sliding_cache_flat_kernel(
    const float4* __restrict__ kc,
    const float4* __restrict__ vc,
    const float4* __restrict__ qc,
    const float4* __restrict__ kt,
    const float4* __restrict__ vt,
    const float4* __restrict__ qt,
    float4* __restrict__ out)
{
    const int c = blockIdx.y;
    const float4* __restrict__ cache = (c == 0) ? kc : (c == 1) ? vc : qc;
    const float4* __restrict__ tok   = (c == 0) ? kt : (c == 1) ? vt : qt;
    float4* __restrict__ ob = out + (size_t)c * CACHE4;

    const unsigned base = blockIdx.x * PER_BLOCK + threadIdx.x;

    unsigned idx[U];
    const float4* __restrict__ src[U];

    #pragma unroll
    for (int k = 0; k < U; k++) {
        idx[k] = base + (unsigned)k * THREADS;
        unsigned pos = idx[k] & SLABMASK;
        src[k] = (pos < TAIL4)
               ? cache + idx[k] + 32
               : tok + ((idx[k] >> 16) << 5) + (pos - TAIL4);
    }

    float4 v[U];
    #pragma unroll
    for (int k = 0; k < U; k++) v[k] = *src[k];      // front-batched LDG.128 x4

    #pragma unroll
    for (int k = 0; k < U; k++) ob[idx[k]] = v[k];   // plain STG.128
}

extern "C" void kernel_launch(void* const* d_in, const int* in_sizes, int n_in,
                              void* d_out, int out_size)
{
    const float4* kc = (const float4*)d_in[0];
    const float4* vc = (const float4*)d_in[1];
    const float4* qc = (const float4*)d_in[2];
    const float4* kt = (const float4*)d_in[3];
    const float4* vt = (const float4*)d_in[4];
    const float4* qt = (const float4*)d_in[5];
    float4* out = (float4*)d_out;

    dim3 grid(CACHE4 / PER_BLOCK, 3, 1);   // 8192 x 3 = 24576 blocks
    sliding_cache_flat_kernel<<<grid, THREADS>>>(kc, vc, qc, kt, vt, qt, out);
}